// round 1
// baseline (speedup 1.0000x reference)
#include <cuda_runtime.h>
#include <math.h>

// Problem constants (fixed by the reference)
#define NB   512
#define NN   1000
#define DD   128
#define NH   8
#define NHID 128
#define NT   256
#define NPAD 1008

__device__ __forceinline__ float warp_max(float v){
    #pragma unroll
    for (int o = 16; o; o >>= 1) v = fmaxf(v, __shfl_xor_sync(0xffffffffu, v, o));
    return v;
}
__device__ __forceinline__ float warp_sum(float v){
    #pragma unroll
    for (int o = 16; o; o >>= 1) v += __shfl_xor_sync(0xffffffffu, v, o);
    return v;
}

__global__ __launch_bounds__(NT) void pointer_attn_kernel(
    const float* __restrict__ state_t,   // [B, 1, 3D]
    const float* __restrict__ context,   // [B, N, D]
    const int*   __restrict__ mask,      // [B, N]
    const float* __restrict__ Wq,        // [3D, HID]
    const float* __restrict__ Wk_mha,    // [D, HID]
    const float* __restrict__ Wv,        // [D, HID]
    const float* __restrict__ Wfc,       // [HID, HID]
    const float* __restrict__ Wk,        // [D, HID]
    const int*   __restrict__ Tptr,     // scalar temperature (int or float bits)
    float*       __restrict__ out)       // [B, N]
{
    __shared__ float  comp[NH][NPAD];     // logits -> unnormalized probs; row 0 reused for u
    __shared__ float4 qk_s[NH][DD/4];     // per-head folded query vector (norm_h folded in)
    __shared__ float  cw_s[NH][DD];       // attention-weighted context per head
    __shared__ float  q_s[NHID];
    __shared__ float  st_s[3*DD];
    __shared__ float  xpre_s[NHID];
    __shared__ float  x_s[NHID];
    __shared__ float4 xk_s[DD/4];         // Wk @ x, norm_p folded in
    __shared__ float  s_h[NH];            // per-head exp sums
    __shared__ float  red_s[8];
    __shared__ float  bc_s[2];

    const int tid = threadIdx.x, b = blockIdx.x;
    const int w = tid >> 5, lane = tid & 31;
    const float* ctx  = context + (size_t)b * NN * DD;
    const int*   mrow = mask    + (size_t)b * NN;

    // ---------------- P0: q = state @ Wq ; qk[h] = Wk_mha[:,hslice] @ q_h ----------------
    for (int i = tid; i < 3*DD; i += NT) st_s[i] = state_t[(size_t)b * 3*DD + i];
    __syncthreads();
    if (tid < NHID) {
        float a = 0.f;
        #pragma unroll 4
        for (int i = 0; i < 3*DD; i++) a = fmaf(st_s[i], Wq[i*NHID + tid], a);
        q_s[tid] = a;
    }
    __syncthreads();
    for (int idx = tid; idx < NH*DD; idx += NT) {
        const int h = idx >> 7, d = idx & 127;
        const float* wr = &Wk_mha[d*NHID + h*16];
        const float* qq = &q_s[h*16];
        float a = 0.f;
        #pragma unroll
        for (int j = 0; j < 16; j++) a = fmaf(wr[j], qq[j], a);
        ((float*)&qk_s[h][0])[d] = 0.25f * a;   // norm_h = 1/sqrt(16)
    }
    __syncthreads();

    // ---------------- P1: comp[h][n] = ctx_n . qk[h]  (masked -> -inf) ----------------
    for (int n = tid; n < NN; n += NT) {
        if (mrow[n]) {
            #pragma unroll
            for (int h = 0; h < NH; h++) comp[h][n] = -INFINITY;
        } else {
            const float4* row = (const float4*)(ctx + (size_t)n * DD);
            float acc[NH];
            #pragma unroll
            for (int h = 0; h < NH; h++) acc[h] = 0.f;
            #pragma unroll 4
            for (int dc = 0; dc < DD/4; dc++) {
                const float4 c = row[dc];
                #pragma unroll
                for (int h = 0; h < NH; h++) {
                    const float4 qv = qk_s[h][dc];
                    acc[h] = fmaf(c.x, qv.x, acc[h]);
                    acc[h] = fmaf(c.y, qv.y, acc[h]);
                    acc[h] = fmaf(c.z, qv.z, acc[h]);
                    acc[h] = fmaf(c.w, qv.w, acc[h]);
                }
            }
            #pragma unroll
            for (int h = 0; h < NH; h++) comp[h][n] = acc[h];
        }
    }
    __syncthreads();

    // ---------------- P2: per-head softmax stats; comp <- exp(comp - max) ----------------
    {
        float m = -INFINITY;
        for (int n = lane; n < NN; n += 32) m = fmaxf(m, comp[w][n]);
        m = warp_max(m);
        float s = 0.f;
        for (int n = lane; n < NN; n += 32) {
            const float p = __expf(comp[w][n] - m);   // exp(-inf)=0 for masked
            comp[w][n] = p;
            s += p;
        }
        s = warp_sum(s);
        if (lane == 0) s_h[w] = s;
    }
    __syncthreads();

    // ---------------- P3: cw[h] = (1/s) * sum_n p[h][n] * ctx_n ----------------
    {
        const int h = w, dc = lane;      // warp per head, lane owns 4 d's -> coalesced rows
        float4 a = make_float4(0.f, 0.f, 0.f, 0.f);
        for (int n = 0; n < NN; n++) {
            const float p = comp[h][n];
            if (p != 0.f) {              // uniform branch per warp: skip masked/underflow
                const float4 c = ((const float4*)(ctx + (size_t)n * DD))[dc];
                a.x = fmaf(p, c.x, a.x); a.y = fmaf(p, c.y, a.y);
                a.z = fmaf(p, c.z, a.z); a.w = fmaf(p, c.w, a.w);
            }
        }
        const float inv = 1.f / s_h[h];
        cw_s[h][4*dc+0] = a.x * inv;  cw_s[h][4*dc+1] = a.y * inv;
        cw_s[h][4*dc+2] = a.z * inv;  cw_s[h][4*dc+3] = a.w * inv;
    }
    __syncthreads();

    // ---------------- P4: x = (cw @ Wv_slices) @ Wfc ; xk = norm_p * (Wk @ x) ----------------
    if (tid < NHID) {                        // x_pre[col] = cw[h] . Wv[:,col]
        const int h = tid >> 4;
        float a = 0.f;
        #pragma unroll 4
        for (int d = 0; d < DD; d++) a = fmaf(cw_s[h][d], Wv[d*NHID + tid], a);
        xpre_s[tid] = a;
    }
    __syncthreads();
    if (tid < NHID) {                        // x = x_pre @ Wfc
        float a = 0.f;
        #pragma unroll 4
        for (int i = 0; i < NHID; i++) a = fmaf(xpre_s[i], Wfc[i*NHID + tid], a);
        x_s[tid] = a;
    }
    __syncthreads();
    if (tid < DD) {                          // xk[d] = norm_p * Wk[d,:] . x
        const float* wr = &Wk[tid*NHID];
        float a = 0.f;
        #pragma unroll 4
        for (int j = 0; j < NHID; j++) a = fmaf(wr[j], x_s[j], a);
        ((float*)xk_s)[tid] = a * 0.08838834764831845f;   // 1/sqrt(128)
    }
    __syncthreads();

    // ---------------- P5: u[n] = tanh(ctx_n . xk)*5, masked -> -inf ----------------
    float* u = &comp[0][0];
    for (int n = tid; n < NN; n += NT) {
        float val;
        if (mrow[n]) {
            val = -INFINITY;
        } else {
            const float4* row = (const float4*)(ctx + (size_t)n * DD);
            float acc = 0.f;
            #pragma unroll 4
            for (int dc = 0; dc < DD/4; dc++) {
                const float4 c = row[dc];
                const float4 k = xk_s[dc];
                acc = fmaf(c.x, k.x, acc); acc = fmaf(c.y, k.y, acc);
                acc = fmaf(c.z, k.z, acc); acc = fmaf(c.w, k.w, acc);
            }
            val = tanhf(acc) * 5.f;
        }
        u[n] = val;
    }
    __syncthreads();

    // ---------------- P6: temperature softmax over n ----------------
    // read T robustly (int 1 or float 1.0 bit patterns)
    const int   Ti = *Tptr;
    const float Tv = (Ti > 0 && Ti < 1000000) ? (float)Ti : __int_as_float(Ti);
    const float invT = 1.f / Tv;

    float m = -INFINITY;
    for (int n = tid; n < NN; n += NT) m = fmaxf(m, u[n]);
    m = warp_max(m);
    if (lane == 0) red_s[w] = m;
    __syncthreads();
    if (w == 0) {
        float v = (lane < 8) ? red_s[lane] : -INFINITY;
        v = warp_max(v);
        if (lane == 0) bc_s[0] = v;
    }
    __syncthreads();
    const float umax = bc_s[0];

    float s = 0.f;
    for (int n = tid; n < NN; n += NT) {
        const float e = __expf((u[n] - umax) * invT);
        u[n] = e;
        s += e;
    }
    s = warp_sum(s);
    __syncthreads();                 // red_s reuse
    if (lane == 0) red_s[w] = s;
    __syncthreads();
    if (w == 0) {
        float v = (lane < 8) ? red_s[lane] : 0.f;
        v = warp_sum(v);
        if (lane == 0) bc_s[1] = v;
    }
    __syncthreads();
    const float invS = 1.f / bc_s[1];

    float* orow = out + (size_t)b * NN;
    for (int n = tid; n < NN; n += NT) orow[n] = u[n] * invS;
}

extern "C" void kernel_launch(void* const* d_in, const int* in_sizes, int n_in,
                              void* d_out, int out_size)
{
    const float* state_t = (const float*)d_in[0];
    const float* context = (const float*)d_in[1];
    const int*   mask    = (const int*)  d_in[2];
    const float* Wq      = (const float*)d_in[3];
    const float* Wk_mha  = (const float*)d_in[4];
    const float* Wv      = (const float*)d_in[5];
    const float* Wfc     = (const float*)d_in[6];
    const float* Wk      = (const float*)d_in[7];
    const int*   Tptr    = (const int*)  d_in[8];
    float* out = (float*)d_out;

    pointer_attn_kernel<<<NB, NT>>>(state_t, context, mask, Wq, Wk_mha,
                                    Wv, Wfc, Wk, Tptr, out);
}

// round 2
// speedup vs baseline: 1.0002x; 1.0002x over previous
#include <cuda_runtime.h>
#include <math.h>

// Problem constants (fixed by the reference)
#define NB   512
#define NN   1000
#define DD   128
#define NH   8
#define NHID 128
#define NT   256
#define NPAD 1008

__device__ __forceinline__ float warp_max(float v){
    #pragma unroll
    for (int o = 16; o; o >>= 1) v = fmaxf(v, __shfl_xor_sync(0xffffffffu, v, o));
    return v;
}
__device__ __forceinline__ float warp_sum(float v){
    #pragma unroll
    for (int o = 16; o; o >>= 1) v += __shfl_xor_sync(0xffffffffu, v, o);
    return v;
}

__global__ __launch_bounds__(NT) void pointer_attn_kernel(
    const float* __restrict__ state_t,   // [B, 1, 3D]
    const float* __restrict__ context,   // [B, N, D]
    const int*   __restrict__ mask,      // [B, N]
    const float* __restrict__ Wq,        // [3D, HID]
    const float* __restrict__ Wk_mha,    // [D, HID]
    const float* __restrict__ Wv,        // [D, HID]
    const float* __restrict__ Wfc,       // [HID, HID]
    const float* __restrict__ Wk,        // [D, HID]
    const int*   __restrict__ Tptr,     // scalar temperature (int or float bits)
    float*       __restrict__ out)       // [B, N]
{
    __shared__ float  comp[NH][NPAD];     // logits -> unnormalized probs; row 0 reused for u
    __shared__ float4 qk_s[NH][DD/4];     // per-head folded query vector (norm_h folded in)
    __shared__ float  cw_s[NH][DD];       // attention-weighted context per head
    __shared__ float  q_s[NHID];
    __shared__ float  st_s[3*DD];
    __shared__ float  xpre_s[NHID];
    __shared__ float  x_s[NHID];
    __shared__ float4 xk_s[DD/4];         // Wk @ x, norm_p folded in
    __shared__ float  s_h[NH];            // per-head exp sums
    __shared__ float  red_s[8];
    __shared__ float  bc_s[2];

    const int tid = threadIdx.x, b = blockIdx.x;
    const int w = tid >> 5, lane = tid & 31;
    const float* ctx  = context + (size_t)b * NN * DD;
    const int*   mrow = mask    + (size_t)b * NN;

    // ---------------- P0: q = state @ Wq ; qk[h] = Wk_mha[:,hslice] @ q_h ----------------
    for (int i = tid; i < 3*DD; i += NT) st_s[i] = state_t[(size_t)b * 3*DD + i];
    __syncthreads();
    if (tid < NHID) {
        float a = 0.f;
        #pragma unroll 4
        for (int i = 0; i < 3*DD; i++) a = fmaf(st_s[i], Wq[i*NHID + tid], a);
        q_s[tid] = a;
    }
    __syncthreads();
    for (int idx = tid; idx < NH*DD; idx += NT) {
        const int h = idx >> 7, d = idx & 127;
        const float* wr = &Wk_mha[d*NHID + h*16];
        const float* qq = &q_s[h*16];
        float a = 0.f;
        #pragma unroll
        for (int j = 0; j < 16; j++) a = fmaf(wr[j], qq[j], a);
        ((float*)&qk_s[h][0])[d] = 0.25f * a;   // norm_h = 1/sqrt(16)
    }
    __syncthreads();

    // ---------------- P1: comp[h][n] = ctx_n . qk[h]  (masked -> -inf) ----------------
    for (int n = tid; n < NN; n += NT) {
        if (mrow[n]) {
            #pragma unroll
            for (int h = 0; h < NH; h++) comp[h][n] = -INFINITY;
        } else {
            const float4* row = (const float4*)(ctx + (size_t)n * DD);
            float acc[NH];
            #pragma unroll
            for (int h = 0; h < NH; h++) acc[h] = 0.f;
            #pragma unroll 4
            for (int dc = 0; dc < DD/4; dc++) {
                const float4 c = row[dc];
                #pragma unroll
                for (int h = 0; h < NH; h++) {
                    const float4 qv = qk_s[h][dc];
                    acc[h] = fmaf(c.x, qv.x, acc[h]);
                    acc[h] = fmaf(c.y, qv.y, acc[h]);
                    acc[h] = fmaf(c.z, qv.z, acc[h]);
                    acc[h] = fmaf(c.w, qv.w, acc[h]);
                }
            }
            #pragma unroll
            for (int h = 0; h < NH; h++) comp[h][n] = acc[h];
        }
    }
    __syncthreads();

    // ---------------- P2: per-head softmax stats; comp <- exp(comp - max) ----------------
    {
        float m = -INFINITY;
        for (int n = lane; n < NN; n += 32) m = fmaxf(m, comp[w][n]);
        m = warp_max(m);
        float s = 0.f;
        for (int n = lane; n < NN; n += 32) {
            const float p = __expf(comp[w][n] - m);   // exp(-inf)=0 for masked
            comp[w][n] = p;
            s += p;
        }
        s = warp_sum(s);
        if (lane == 0) s_h[w] = s;
    }
    __syncthreads();

    // ---------------- P3: cw[h] = (1/s) * sum_n p[h][n] * ctx_n ----------------
    {
        const int h = w, dc = lane;      // warp per head, lane owns 4 d's -> coalesced rows
        float4 a = make_float4(0.f, 0.f, 0.f, 0.f);
        for (int n = 0; n < NN; n++) {
            const float p = comp[h][n];
            if (p != 0.f) {              // uniform branch per warp: skip masked/underflow
                const float4 c = ((const float4*)(ctx + (size_t)n * DD))[dc];
                a.x = fmaf(p, c.x, a.x); a.y = fmaf(p, c.y, a.y);
                a.z = fmaf(p, c.z, a.z); a.w = fmaf(p, c.w, a.w);
            }
        }
        const float inv = 1.f / s_h[h];
        cw_s[h][4*dc+0] = a.x * inv;  cw_s[h][4*dc+1] = a.y * inv;
        cw_s[h][4*dc+2] = a.z * inv;  cw_s[h][4*dc+3] = a.w * inv;
    }
    __syncthreads();

    // ---------------- P4: x = (cw @ Wv_slices) @ Wfc ; xk = norm_p * (Wk @ x) ----------------
    if (tid < NHID) {                        // x_pre[col] = cw[h] . Wv[:,col]
        const int h = tid >> 4;
        float a = 0.f;
        #pragma unroll 4
        for (int d = 0; d < DD; d++) a = fmaf(cw_s[h][d], Wv[d*NHID + tid], a);
        xpre_s[tid] = a;
    }
    __syncthreads();
    if (tid < NHID) {                        // x = x_pre @ Wfc
        float a = 0.f;
        #pragma unroll 4
        for (int i = 0; i < NHID; i++) a = fmaf(xpre_s[i], Wfc[i*NHID + tid], a);
        x_s[tid] = a;
    }
    __syncthreads();
    if (tid < DD) {                          // xk[d] = norm_p * Wk[d,:] . x
        const float* wr = &Wk[tid*NHID];
        float a = 0.f;
        #pragma unroll 4
        for (int j = 0; j < NHID; j++) a = fmaf(wr[j], x_s[j], a);
        ((float*)xk_s)[tid] = a * 0.08838834764831845f;   // 1/sqrt(128)
    }
    __syncthreads();

    // ---------------- P5: u[n] = tanh(ctx_n . xk)*5, masked -> -inf ----------------
    float* u = &comp[0][0];
    for (int n = tid; n < NN; n += NT) {
        float val;
        if (mrow[n]) {
            val = -INFINITY;
        } else {
            const float4* row = (const float4*)(ctx + (size_t)n * DD);
            float acc = 0.f;
            #pragma unroll 4
            for (int dc = 0; dc < DD/4; dc++) {
                const float4 c = row[dc];
                const float4 k = xk_s[dc];
                acc = fmaf(c.x, k.x, acc); acc = fmaf(c.y, k.y, acc);
                acc = fmaf(c.z, k.z, acc); acc = fmaf(c.w, k.w, acc);
            }
            val = tanhf(acc) * 5.f;
        }
        u[n] = val;
    }
    __syncthreads();

    // ---------------- P6: temperature softmax over n ----------------
    // read T robustly (int 1 or float 1.0 bit patterns)
    const int   Ti = *Tptr;
    const float Tv = (Ti > 0 && Ti < 1000000) ? (float)Ti : __int_as_float(Ti);
    const float invT = 1.f / Tv;

    float m = -INFINITY;
    for (int n = tid; n < NN; n += NT) m = fmaxf(m, u[n]);
    m = warp_max(m);
    if (lane == 0) red_s[w] = m;
    __syncthreads();
    if (w == 0) {
        float v = (lane < 8) ? red_s[lane] : -INFINITY;
        v = warp_max(v);
        if (lane == 0) bc_s[0] = v;
    }
    __syncthreads();
    const float umax = bc_s[0];

    float s = 0.f;
    for (int n = tid; n < NN; n += NT) {
        const float e = __expf((u[n] - umax) * invT);
        u[n] = e;
        s += e;
    }
    s = warp_sum(s);
    __syncthreads();                 // red_s reuse
    if (lane == 0) red_s[w] = s;
    __syncthreads();
    if (w == 0) {
        float v = (lane < 8) ? red_s[lane] : 0.f;
        v = warp_sum(v);
        if (lane == 0) bc_s[1] = v;
    }
    __syncthreads();
    const float invS = 1.f / bc_s[1];

    float* orow = out + (size_t)b * NN;
    for (int n = tid; n < NN; n += NT) orow[n] = u[n] * invS;
}

extern "C" void kernel_launch(void* const* d_in, const int* in_sizes, int n_in,
                              void* d_out, int out_size)
{
    const float* state_t = (const float*)d_in[0];
    const float* context = (const float*)d_in[1];
    const int*   mask    = (const int*)  d_in[2];
    const float* Wq      = (const float*)d_in[3];
    const float* Wk_mha  = (const float*)d_in[4];
    const float* Wv      = (const float*)d_in[5];
    const float* Wfc     = (const float*)d_in[6];
    const float* Wk      = (const float*)d_in[7];
    const int*   Tptr    = (const int*)  d_in[8];
    float* out = (float*)d_out;

    pointer_attn_kernel<<<NB, NT>>>(state_t, context, mask, Wq, Wk_mha,
                                    Wv, Wfc, Wk, Tptr, out);
}

// round 3
// speedup vs baseline: 1.1959x; 1.1957x over previous
#include <cuda_runtime.h>
#include <math.h>

#define NB   512
#define NN   1000
#define DD   128
#define NH   8
#define NHID 128
#define NT   256
#define NPAD 1008

__device__ __forceinline__ float warp_max(float v){
    #pragma unroll
    for (int o = 16; o; o >>= 1) v = fmaxf(v, __shfl_xor_sync(0xffffffffu, v, o));
    return v;
}
__device__ __forceinline__ float warp_sum(float v){
    #pragma unroll
    for (int o = 16; o; o >>= 1) v += __shfl_xor_sync(0xffffffffu, v, o);
    return v;
}
__device__ __forceinline__ float dot4(float4 c, float4 q){
    return fmaf(c.w, q.w, fmaf(c.z, q.z, fmaf(c.y, q.y, c.x * q.x)));
}
// Butterfly reduce-scatter of 8 per-lane partials across the warp.
// On return, every lane holds the full warp-sum of head h = (lane>>2)&7.
__device__ __forceinline__ float reduce8(float* a, int lane){
    const unsigned F = 0xffffffffu;
    const bool b4 = lane & 16, b3 = lane & 8, b2 = lane & 4;
    #pragma unroll
    for (int i = 0; i < 4; i++) {
        float snd = b4 ? a[i] : a[i+4];
        float rcv = __shfl_xor_sync(F, snd, 16);
        a[i] = (b4 ? a[i+4] : a[i]) + rcv;
    }
    #pragma unroll
    for (int i = 0; i < 2; i++) {
        float snd = b3 ? a[i] : a[i+2];
        float rcv = __shfl_xor_sync(F, snd, 8);
        a[i] = (b3 ? a[i+2] : a[i]) + rcv;
    }
    {
        float snd = b2 ? a[0] : a[1];
        float rcv = __shfl_xor_sync(F, snd, 4);
        a[0] = (b2 ? a[1] : a[0]) + rcv;
    }
    a[0] += __shfl_xor_sync(F, a[0], 2);
    a[0] += __shfl_xor_sync(F, a[0], 1);
    return a[0];
}

__global__ __launch_bounds__(NT) void pointer_attn_kernel(
    const float* __restrict__ state_t,   // [B, 3D]
    const float* __restrict__ context,   // [B, N, D]
    const int*   __restrict__ mask,      // [B, N]
    const float* __restrict__ Wq,        // [3D, HID]
    const float* __restrict__ Wk_mha,    // [D, HID]
    const float* __restrict__ Wv,        // [D, HID]
    const float* __restrict__ Wfc,       // [HID, HID]
    const float* __restrict__ Wk,        // [D, HID]
    const int*   __restrict__ Tptr,
    float*       __restrict__ out)       // [B, N]
{
    __shared__ float  comp_s[NH * NPAD];   // logits -> probs; later reused: u[] in first 1008
    __shared__ float4 qk_s[NH * 32];       // per-head folded query vecs (norm folded)
    __shared__ float  cw_s[NH * DD];       // unnormalized attn-weighted context
    __shared__ float  st_s[3*DD];
    __shared__ float  q_s[NHID], xpre_s[NHID], x_s[NHID];
    __shared__ float4 xk_s[32];
    __shared__ float  wmax_s[NH * 8];      // [head][warp] per-warp logit maxima
    __shared__ float  s_h[NH];
    __shared__ float  red_s[8], bc_s[2];

    const int tid = threadIdx.x, b = blockIdx.x;
    const int w = tid >> 5, lane = tid & 31;
    const int myh = (lane >> 2) & 7;
    const float*  ctx  = context + (size_t)b * NN * DD;
    const float4* ctx4 = (const float4*)ctx;
    const int*    mrow = mask + (size_t)b * NN;

    // ---------------- P0: q = state @ Wq ; qk[h] = norm_h * (Wk_mha[:,hslice] @ q_h) --------
    for (int i = tid; i < 3*DD; i += NT) st_s[i] = state_t[(size_t)b * 3*DD + i];
    for (int i = tid; i < NH*DD; i += NT) cw_s[i] = 0.f;
    __syncthreads();
    if (tid < NHID) {
        float a = 0.f;
        #pragma unroll 4
        for (int i = 0; i < 3*DD; i++) a = fmaf(st_s[i], Wq[i*NHID + tid], a);
        q_s[tid] = a;
    }
    __syncthreads();
    for (int idx = tid; idx < NH*DD; idx += NT) {
        const int h = idx >> 7, d = idx & 127;
        const float* wr = &Wk_mha[d*NHID + h*16];
        const float* qq = &q_s[h*16];
        float a = 0.f;
        #pragma unroll
        for (int j = 0; j < 16; j++) a = fmaf(wr[j], qq[j], a);
        ((float*)qk_s)[h*DD + d] = 0.25f * a;        // norm_h = 1/sqrt(16)
    }
    __syncthreads();

    // ---------------- Pass A: logits, warp-per-row coalesced; track per-head warp max ------
    {
        float4 qk_r[NH];
        #pragma unroll
        for (int h = 0; h < NH; h++) qk_r[h] = qk_s[h*32 + lane];
        float mymax = -INFINITY;
        for (int n = w; n < NN; n += 8) {
            if (mrow[n]) {
                if ((lane & 3) == 0) comp_s[myh*NPAD + n] = -INFINITY;
            } else {
                const float4 c = ctx4[(size_t)n*32 + lane];
                float a[NH];
                #pragma unroll
                for (int h = 0; h < NH; h++) a[h] = dot4(c, qk_r[h]);
                const float v = reduce8(a, lane);     // all lanes: head myh total
                mymax = fmaxf(mymax, v);
                if ((lane & 3) == 0) comp_s[myh*NPAD + n] = v;
            }
        }
        if ((lane & 3) == 0) wmax_s[myh*8 + w] = mymax;
    }
    __syncthreads();

    // ---------------- Pass B: per-head softmax (warp w = head w) ----------------
    {
        float t = (lane < 8) ? wmax_s[w*8 + lane] : -INFINITY;
        const float M = warp_max(t);
        float s = 0.f;
        for (int n = lane; n < NN; n += 32) {
            const float p = __expf(comp_s[w*NPAD + n] - M);   // exp(-inf)=0 masked
            comp_s[w*NPAD + n] = p;
            s += p;
        }
        s = warp_sum(s);
        if (lane == 0) s_h[w] = s;
    }
    __syncthreads();

    // ---------------- Pass C: cw[h] += p[h][n] * ctx_n (coalesced, all heads at once) ------
    {
        float4 acc[NH];
        #pragma unroll
        for (int h = 0; h < NH; h++) acc[h] = make_float4(0.f, 0.f, 0.f, 0.f);
        for (int n = w; n < NN; n += 8) {
            if (!mrow[n]) {
                const float4 c = ctx4[(size_t)n*32 + lane];
                #pragma unroll
                for (int h = 0; h < NH; h++) {
                    const float p = comp_s[h*NPAD + n];       // smem broadcast
                    acc[h].x = fmaf(p, c.x, acc[h].x);
                    acc[h].y = fmaf(p, c.y, acc[h].y);
                    acc[h].z = fmaf(p, c.z, acc[h].z);
                    acc[h].w = fmaf(p, c.w, acc[h].w);
                }
            }
        }
        #pragma unroll
        for (int h = 0; h < NH; h++) {
            float* dst = &cw_s[h*DD + 4*lane];
            atomicAdd(dst+0, acc[h].x);
            atomicAdd(dst+1, acc[h].y);
            atomicAdd(dst+2, acc[h].z);
            atomicAdd(dst+3, acc[h].w);
        }
    }
    __syncthreads();

    // ---------------- P4: x = (cw/s @ Wv_slices) @ Wfc ; xk = norm_p * (Wk @ x) ------------
    if (tid < NHID) {
        const int h = tid >> 4;
        float a = 0.f;
        #pragma unroll 4
        for (int d = 0; d < DD; d++) a = fmaf(cw_s[h*DD + d], Wv[d*NHID + tid], a);
        xpre_s[tid] = a / s_h[h];                     // fold softmax normalization
    }
    __syncthreads();
    if (tid < NHID) {
        float a = 0.f;
        #pragma unroll 4
        for (int i = 0; i < NHID; i++) a = fmaf(xpre_s[i], Wfc[i*NHID + tid], a);
        x_s[tid] = a;
    }
    __syncthreads();
    if (tid < DD) {
        const float* wr = &Wk[tid*NHID];
        float a = 0.f;
        #pragma unroll 4
        for (int j = 0; j < NHID; j++) a = fmaf(wr[j], x_s[j], a);
        ((float*)xk_s)[tid] = a * 0.08838834764831845f;   // 1/sqrt(128)
    }
    __syncthreads();

    // ---------------- P5: u[n] = tanh(ctx_n . xk)*5 (warp-per-row) ----------------
    float* u = comp_s;   // reuse; only [0,1000) used
    {
        const float4 xk_r = xk_s[lane];
        for (int n = w; n < NN; n += 8) {
            if (mrow[n]) {
                if (lane == 0) u[n] = -INFINITY;
            } else {
                const float4 c = ctx4[(size_t)n*32 + lane];
                float a = warp_sum(dot4(c, xk_r));
                if (lane == 0) u[n] = tanhf(a) * 5.f;
            }
        }
    }
    __syncthreads();

    // ---------------- P6: temperature softmax over n ----------------
    const int   Ti = *Tptr;
    const float Tv = (Ti > 0 && Ti < 1000000) ? (float)Ti : __int_as_float(Ti);
    const float invT = 1.f / Tv;

    float m = -INFINITY;
    for (int n = tid; n < NN; n += NT) m = fmaxf(m, u[n]);
    m = warp_max(m);
    if (lane == 0) red_s[w] = m;
    __syncthreads();
    if (w == 0) {
        float v = (lane < 8) ? red_s[lane] : -INFINITY;
        v = warp_max(v);
        if (lane == 0) bc_s[0] = v;
    }
    __syncthreads();
    const float umax = bc_s[0];

    float s = 0.f;
    for (int n = tid; n < NN; n += NT) {
        const float e = __expf((u[n] - umax) * invT);
        u[n] = e;
        s += e;
    }
    s = warp_sum(s);
    __syncthreads();
    if (lane == 0) red_s[w] = s;
    __syncthreads();
    if (w == 0) {
        float v = (lane < 8) ? red_s[lane] : 0.f;
        v = warp_sum(v);
        if (lane == 0) bc_s[1] = v;
    }
    __syncthreads();
    const float invS = 1.f / bc_s[1];

    float* orow = out + (size_t)b * NN;
    for (int n = tid; n < NN; n += NT) orow[n] = u[n] * invS;
}

extern "C" void kernel_launch(void* const* d_in, const int* in_sizes, int n_in,
                              void* d_out, int out_size)
{
    const float* state_t = (const float*)d_in[0];
    const float* context = (const float*)d_in[1];
    const int*   mask    = (const int*)  d_in[2];
    const float* Wq      = (const float*)d_in[3];
    const float* Wk_mha  = (const float*)d_in[4];
    const float* Wv      = (const float*)d_in[5];
    const float* Wfc     = (const float*)d_in[6];
    const float* Wk      = (const float*)d_in[7];
    const int*   Tptr    = (const int*)  d_in[8];
    float* out = (float*)d_out;

    pointer_attn_kernel<<<NB, NT>>>(state_t, context, mask, Wq, Wk_mha,
                                    Wv, Wfc, Wk, Tptr, out);
}

// round 5
// speedup vs baseline: 1.5729x; 1.3153x over previous
#include <cuda_runtime.h>
#include <math.h>

#define NB   512
#define NN   1000
#define DD   128
#define NH   8
#define NHID 128
#define NT   256
#define NPAD 1009   // odd stride: conflict-free strided smem access

__device__ __forceinline__ float warp_max(float v){
    #pragma unroll
    for (int o = 16; o; o >>= 1) v = fmaxf(v, __shfl_xor_sync(0xffffffffu, v, o));
    return v;
}
__device__ __forceinline__ float warp_sum(float v){
    #pragma unroll
    for (int o = 16; o; o >>= 1) v += __shfl_xor_sync(0xffffffffu, v, o);
    return v;
}
__device__ __forceinline__ float dot4(float4 c, float4 q){
    return fmaf(c.w, q.w, fmaf(c.z, q.z, fmaf(c.y, q.y, c.x * q.x)));
}
__device__ __forceinline__ float tanh_fast(float x){
    // tanh(x) = 1 - 2/(e^{2x}+1); exact limits at +-inf via __expf saturation
    const float e = __expf(2.f * x);
    return 1.f - __fdividef(2.f, e + 1.f);
}
// Butterfly reduce of 16 per-lane partials (layout idx = 2h + r).
// Returns full warp-sum of idx ((lane>>1)&15) on every lane: h=(lane>>2)&7, r=(lane>>1)&1.
__device__ __forceinline__ float reduce16(float* a, int lane){
    const unsigned F = 0xffffffffu;
    const bool b4 = lane & 16, b3 = lane & 8, b2 = lane & 4, b1 = lane & 2;
    #pragma unroll
    for (int i = 0; i < 8; i++) {
        float snd = b4 ? a[i] : a[i+8];
        float rcv = __shfl_xor_sync(F, snd, 16);
        a[i] = (b4 ? a[i+8] : a[i]) + rcv;
    }
    #pragma unroll
    for (int i = 0; i < 4; i++) {
        float snd = b3 ? a[i] : a[i+4];
        float rcv = __shfl_xor_sync(F, snd, 8);
        a[i] = (b3 ? a[i+4] : a[i]) + rcv;
    }
    #pragma unroll
    for (int i = 0; i < 2; i++) {
        float snd = b2 ? a[i] : a[i+2];
        float rcv = __shfl_xor_sync(F, snd, 4);
        a[i] = (b2 ? a[i+2] : a[i]) + rcv;
    }
    {
        float snd = b1 ? a[0] : a[1];
        float rcv = __shfl_xor_sync(F, snd, 2);
        a[0] = (b1 ? a[1] : a[0]) + rcv;
    }
    a[0] += __shfl_xor_sync(F, a[0], 1);
    return a[0];
}

__global__ __launch_bounds__(NT, 4) void pointer_attn_kernel(
    const float* __restrict__ state_t,   // [B, 3D]
    const float* __restrict__ context,   // [B, N, D]
    const int*   __restrict__ mask,      // [B, N]
    const float* __restrict__ Wq,        // [3D, HID]
    const float* __restrict__ Wk_mha,    // [D, HID]
    const float* __restrict__ Wv,        // [D, HID]
    const float* __restrict__ Wfc,       // [HID, HID]
    const float* __restrict__ Wk,        // [D, HID]
    const int*   __restrict__ Tptr,
    float*       __restrict__ out)       // [B, N]
{
    __shared__ float  comp_s[NH * NPAD];   // [h][i] probs (dense over active rows)
    __shared__ unsigned short list_s[1024];
    __shared__ float4 qk_s[NH * 32];
    __shared__ float  cw_s[NH * DD];
    __shared__ float  st_s[3*DD];
    __shared__ float  q_s[NHID], xpre_s[NHID], x_s[NHID];
    __shared__ float4 xk_s[32];
    __shared__ float  wmax_s[NH * 8];
    __shared__ float  s_h[NH];
    __shared__ int    wsum_s[8];
    __shared__ int    cnt_s;
    __shared__ float  red_s[8], bc_s[2];

    const int tid = threadIdx.x, b = blockIdx.x;
    const int w = tid >> 5, lane = tid & 31;
    const int myh = (lane >> 2) & 7;
    const unsigned F = 0xffffffffu;
    const float*  ctx  = context + (size_t)b * NN * DD;
    const float4* ctx4 = (const float4*)ctx;
    const int*    mrow = mask + (size_t)b * NN;

    // ========== P0a: deterministic compaction of unmasked rows ==========
    {
        int cnt_t = 0; unsigned bits = 0;
        if (tid < 250) {                          // 250*4 = 1000 exactly
            const int4 mv = ((const int4*)mrow)[tid];
            if (mv.x == 0) { bits |= 1u; cnt_t++; }
            if (mv.y == 0) { bits |= 2u; cnt_t++; }
            if (mv.z == 0) { bits |= 4u; cnt_t++; }
            if (mv.w == 0) { bits |= 8u; cnt_t++; }
        }
        int x = cnt_t;
        #pragma unroll
        for (int off = 1; off < 32; off <<= 1) {
            int y = __shfl_up_sync(F, x, off);
            if (lane >= off) x += y;
        }
        if (lane == 31) wsum_s[w] = x;
        // stage state while scan settles
        for (int i = tid; i < 3*DD; i += NT) st_s[i] = state_t[(size_t)b * 3*DD + i];
        for (int i = tid; i < NH*DD; i += NT) cw_s[i] = 0.f;
        __syncthreads();
        if (tid == 0) {
            int run = 0;
            #pragma unroll
            for (int wi = 0; wi < 8; wi++) { int c = wsum_s[wi]; wsum_s[wi] = run; run += c; }
            cnt_s = run;
        }
        __syncthreads();
        int base = wsum_s[w] + (x - cnt_t);
        #pragma unroll
        for (int k = 0; k < 4; k++)
            if (bits & (1u << k)) list_s[base++] = (unsigned short)(tid*4 + k);
    }

    // ========== P0b: q = state @ Wq ; qk[h] = 0.25 * Wk_mha[:,hslice] @ q_h ==========
    if (tid < NHID) {
        float a = 0.f;
        #pragma unroll 4
        for (int i = 0; i < 3*DD; i++) a = fmaf(st_s[i], Wq[i*NHID + tid], a);
        q_s[tid] = a;
    }
    __syncthreads();
    for (int idx = tid; idx < NH*DD; idx += NT) {
        const int h = idx >> 7, d = idx & 127;
        const float* wr = &Wk_mha[d*NHID + h*16];
        const float* qq = &q_s[h*16];
        float a = 0.f;
        #pragma unroll
        for (int j = 0; j < 16; j++) a = fmaf(wr[j], qq[j], a);
        ((float*)qk_s)[h*DD + d] = 0.25f * a;
    }
    __syncthreads();

    const int cnt = cnt_s;

    // ========== Pass A: logits over active rows, 2-row pairs, reduce16 ==========
    {
        float mymax = -INFINITY;
        for (int p = w; 2*p < cnt; p += 8) {
            const int i0 = 2*p;
            const bool has1 = (i0 + 1) < cnt;
            const int n0 = list_s[i0];
            const int n1 = has1 ? list_s[i0+1] : n0;
            const float4 c0 = ctx4[(unsigned)n0*32 + lane];
            const float4 c1 = ctx4[(unsigned)n1*32 + lane];
            float a[16];
            #pragma unroll
            for (int h = 0; h < NH; h++) {
                const float4 qv = qk_s[h*32 + lane];
                a[2*h]   = dot4(c0, qv);
                a[2*h+1] = dot4(c1, qv);
            }
            const float v = reduce16(a, lane);
            const int r = (lane >> 1) & 1;
            const bool valid = (r == 0) || has1;
            if (valid) {
                mymax = fmaxf(mymax, v);
                if (!(lane & 1)) comp_s[myh*NPAD + i0 + r] = v;
            }
        }
        float t = mymax;
        t = fmaxf(t, __shfl_xor_sync(F, t, 2));
        t = fmaxf(t, __shfl_xor_sync(F, t, 1));
        if ((lane & 3) == 0) wmax_s[myh*8 + w] = t;
    }
    __syncthreads();

    // ========== Pass B: per-head exp + sum (warp w = head w) ==========
    {
        float t = (lane < 8) ? wmax_s[w*8 + lane] : -INFINITY;
        const float M = warp_max(t);
        float s = 0.f;
        for (int i = lane; i < cnt; i += 32) {
            const float p = __expf(comp_s[w*NPAD + i] - M);
            comp_s[w*NPAD + i] = p;
            s += p;
        }
        s = warp_sum(s);
        if (lane == 0) s_h[w] = s;
    }
    __syncthreads();

    // ========== Pass C: cw[h] += p[h][i] * ctx_row, 2-row pairs, all heads ==========
    {
        float4 acc[NH];
        #pragma unroll
        for (int h = 0; h < NH; h++) acc[h] = make_float4(0.f, 0.f, 0.f, 0.f);
        for (int p = w; 2*p < cnt; p += 8) {
            const int i0 = 2*p;
            const bool has1 = (i0 + 1) < cnt;
            const int n0 = list_s[i0];
            const int n1 = has1 ? list_s[i0+1] : n0;
            const float4 c0 = ctx4[(unsigned)n0*32 + lane];
            const float4 c1 = ctx4[(unsigned)n1*32 + lane];
            #pragma unroll
            for (int h = 0; h < NH; h++) {
                const float p0 = comp_s[h*NPAD + i0];
                float p1 = comp_s[h*NPAD + i0 + 1];
                p1 = has1 ? p1 : 0.f;
                acc[h].x = fmaf(p0, c0.x, acc[h].x); acc[h].y = fmaf(p0, c0.y, acc[h].y);
                acc[h].z = fmaf(p0, c0.z, acc[h].z); acc[h].w = fmaf(p0, c0.w, acc[h].w);
                acc[h].x = fmaf(p1, c1.x, acc[h].x); acc[h].y = fmaf(p1, c1.y, acc[h].y);
                acc[h].z = fmaf(p1, c1.z, acc[h].z); acc[h].w = fmaf(p1, c1.w, acc[h].w);
            }
        }
        #pragma unroll
        for (int h = 0; h < NH; h++) {
            float* dst = &cw_s[h*DD + 4*lane];
            atomicAdd(dst+0, acc[h].x);
            atomicAdd(dst+1, acc[h].y);
            atomicAdd(dst+2, acc[h].z);
            atomicAdd(dst+3, acc[h].w);
        }
    }
    __syncthreads();

    // ========== P4: x = (cw/s @ Wv) @ Wfc ; xk = norm_p * (Wk @ x) ==========
    if (tid < NHID) {
        const int h = tid >> 4;
        float a = 0.f;
        #pragma unroll 4
        for (int d = 0; d < DD; d++) a = fmaf(cw_s[h*DD + d], Wv[d*NHID + tid], a);
        xpre_s[tid] = a / s_h[h];
    }
    __syncthreads();
    if (tid < NHID) {
        float a = 0.f;
        #pragma unroll 4
        for (int i = 0; i < NHID; i++) a = fmaf(xpre_s[i], Wfc[i*NHID + tid], a);
        x_s[tid] = a;
    }
    __syncthreads();
    if (tid < DD) {
        const float* wr = &Wk[tid*NHID];
        float a = 0.f;
        #pragma unroll 4
        for (int j = 0; j < NHID; j++) a = fmaf(wr[j], x_s[j], a);
        ((float*)xk_s)[tid] = a * 0.08838834764831845f;
    }
    __syncthreads();

    // ========== P5: u[i] = 5*tanh(ctx . xk) over active rows (2-row pairs) ==========
    float* u = comp_s;                  // dense [0, cnt); head-0 prob row reused
    {
        const float4 xk_r = xk_s[lane];
        for (int p = w; 2*p < cnt; p += 8) {
            const int i0 = 2*p;
            const bool has1 = (i0 + 1) < cnt;
            const int n0 = list_s[i0];
            const int n1 = has1 ? list_s[i0+1] : n0;
            const float4 c0 = ctx4[(unsigned)n0*32 + lane];
            const float4 c1 = ctx4[(unsigned)n1*32 + lane];
            float a0 = dot4(c0, xk_r);
            float a1 = dot4(c1, xk_r);
            // reduce2: lanes bit4=0 end with row0 sum, bit4=1 with row1 sum
            float snd = (lane & 16) ? a0 : a1;
            float rcv = __shfl_xor_sync(F, snd, 16);
            float v = ((lane & 16) ? a1 : a0) + rcv;
            v += __shfl_xor_sync(F, v, 8);
            v += __shfl_xor_sync(F, v, 4);
            v += __shfl_xor_sync(F, v, 2);
            v += __shfl_xor_sync(F, v, 1);
            const float uv = tanh_fast(v) * 5.f;
            if (lane == 0) u[i0] = uv;
            if (lane == 16 && has1) u[i0 + 1] = uv;
        }
    }
    __syncthreads();

    // ========== P6: temperature softmax over active rows; scatter via smem ==========
    const int   Ti = *Tptr;
    const float Tv = (Ti > 0 && Ti < 1000000) ? (float)Ti : __int_as_float(Ti);
    const float invT = 1.f / Tv;

    float m = -INFINITY;
    for (int i = tid; i < cnt; i += NT) m = fmaxf(m, u[i]);
    m = warp_max(m);
    if (lane == 0) red_s[w] = m;
    __syncthreads();
    if (w == 0) {
        float v = (lane < 8) ? red_s[lane] : -INFINITY;
        v = warp_max(v);
        if (lane == 0) bc_s[0] = v;
    }
    __syncthreads();
    const float umax = bc_s[0];

    float s = 0.f;
    for (int i = tid; i < cnt; i += NT) {
        const float e = __expf((u[i] - umax) * invT);
        u[i] = e;
        s += e;
    }
    s = warp_sum(s);
    __syncthreads();
    if (lane == 0) red_s[w] = s;
    __syncthreads();
    if (w == 0) {
        float v = (lane < 8) ? red_s[lane] : 0.f;
        v = warp_sum(v);
        if (lane == 0) bc_s[1] = v;
    }
    __syncthreads();
    const float invS = 1.f / bc_s[1];

    // dense -> [N] via smem scatter (uo = comp_s row 1, disjoint from u since cnt<=1000<NPAD)
    float* uo = comp_s + NPAD;
    for (int n = tid; n < NN; n += NT) uo[n] = 0.f;
    __syncthreads();
    for (int i = tid; i < cnt; i += NT) uo[list_s[i]] = u[i] * invS;
    __syncthreads();
    float* orow = out + (size_t)b * NN;
    for (int n = tid; n < NN; n += NT) orow[n] = uo[n];
}

extern "C" void kernel_launch(void* const* d_in, const int* in_sizes, int n_in,
                              void* d_out, int out_size)
{
    const float* state_t = (const float*)d_in[0];
    const float* context = (const float*)d_in[1];
    const int*   mask    = (const int*)  d_in[2];
    const float* Wq      = (const float*)d_in[3];
    const float* Wk_mha  = (const float*)d_in[4];
    const float* Wv      = (const float*)d_in[5];
    const float* Wfc     = (const float*)d_in[6];
    const float* Wk      = (const float*)d_in[7];
    const int*   Tptr    = (const int*)  d_in[8];
    float* out = (float*)d_out;

    pointer_attn_kernel<<<NB, NT>>>(state_t, context, mask, Wq, Wk_mha,
                                    Wv, Wfc, Wk, Tptr, out);
}